// round 4
// baseline (speedup 1.0000x reference)
#include <cuda_runtime.h>
#include <math.h>

#define B_   16
#define C_   384
#define CH_  64
#define CF_  193
#define HW_  16384   // 128*128

__device__ float g_y0[B_ * C_];     // pooled means
__device__ float g_ys[B_ * C_];     // sigmoid gate y (published by k_spec kg==0)
__device__ float g_rRe[B_ * CF_];   // spectral re
__device__ float g_rIm[B_ * CF_];   // spectral im
__device__ float g_cos[C_];         // twiddle cos(2*pi*m/384)
__device__ float g_sin[C_];
__device__ float g_W1c[CH_ * C_];   // W1[j, c, 1, 1] compacted  [j][c]
__device__ float g_W2cT[CH_ * C_];  // W2[c, j, 1, 1] compact + transposed [j][c]

// ---------------------------------------------------------------------------
// Kernel 1: global average pool (~54us, HBM roofline). Side duties on the
// first 13 blocks: twiddle table + center-tap weight compaction.
// ---------------------------------------------------------------------------
__global__ __launch_bounds__(256) void pool_kernel(
    const float* __restrict__ x,
    const float* __restrict__ W1, const float* __restrict__ W2)
{
    const int bid = blockIdx.x;
    if (bid == 0) {
        for (int m = threadIdx.x; m < C_; m += 256) {
            float sv, cv;
            sincosf((float)m * (6.283185307179586f / (float)C_), &sv, &cv);
            g_cos[m] = cv;
            g_sin[m] = sv;
        }
    } else if (bid <= 6) {                       // W1 center taps: 24576 elems
        for (int e = (bid - 1) * 4096 + threadIdx.x; e < bid * 4096; e += 256) {
            int j = e / C_, n = e - j * C_;
            g_W1c[e] = W1[j * (C_ * 9) + n * 9 + 4];
        }
    } else if (bid <= 12) {                      // W2 center taps, transposed
        for (int e = (bid - 7) * 4096 + threadIdx.x; e < (bid - 6) * 4096; e += 256) {
            int j = e / C_, c = e - j * C_;
            g_W2cT[e] = W2[c * (CH_ * 9) + j * 9 + 4];
        }
    }

    const float4* __restrict__ p =
        reinterpret_cast<const float4*>(x + (size_t)bid * HW_);
    float s = 0.f;
#pragma unroll
    for (int i = 0; i < 16; ++i) {
        float4 v = p[threadIdx.x + 256 * i];
        s += (v.x + v.y) + (v.z + v.w);
    }
#pragma unroll
    for (int o = 16; o > 0; o >>= 1) s += __shfl_down_sync(0xffffffffu, s, o);
    __shared__ float ws[8];
    if ((threadIdx.x & 31) == 0) ws[threadIdx.x >> 5] = s;
    __syncthreads();
    if (threadIdx.x < 8) {
        s = ws[threadIdx.x];
#pragma unroll
        for (int o = 4; o > 0; o >>= 1) s += __shfl_down_sync(0xffu, s, o);
        if (threadIdx.x == 0) g_y0[bid] = s * (1.f / (float)HW_);
    }
}

// ---------------------------------------------------------------------------
// Kernel 2: fused SE gate + spectral bins. Block = (b, group of 8 bins),
// grid = 16*25 = 400. Each block redundantly computes h (64) and y (384)
// from g_y0 using the compacted weights, then does its DFT bins + Ws matvecs.
// kg==0 blocks publish y to g_ys for the irfft kernel.
// ---------------------------------------------------------------------------
__global__ __launch_bounds__(256) void k_spec(
    const float* __restrict__ b1, const float* __restrict__ b2,
    const float* __restrict__ Ws1, const float* __restrict__ bs1,
    const float* __restrict__ Ws2, const float* __restrict__ bs2)
{
    const int b    = blockIdx.x / 25;
    const int kg   = blockIdx.x - b * 25;
    const int t    = threadIdx.x;
    const int w    = t >> 5;
    const int lane = t & 31;

    __shared__ float y0s[C_], ys[C_], cT[C_], sT[C_], hs[CH_];

    for (int m = t; m < C_; m += 256) {
        y0s[m] = g_y0[b * C_ + m];
        cT[m]  = g_cos[m];
        sT[m]  = g_sin[m];
    }
    __syncthreads();

    // h[j] = relu(y0 . W1c[j,:] + b1[j])  -- warp per j, 8 rounds
    for (int j = w; j < CH_; j += 8) {
        float acc = 0.f;
#pragma unroll
        for (int i = 0; i < 12; ++i) {
            int n = lane + 32 * i;
            acc += y0s[n] * g_W1c[j * C_ + n];
        }
#pragma unroll
        for (int o = 16; o > 0; o >>= 1) acc += __shfl_down_sync(0xffffffffu, acc, o);
        if (lane == 0) hs[j] = fmaxf(acc + b1[j], 0.f);
    }
    __syncthreads();

    // y[c] = sigmoid(h . W2cT[:,c] + b2[c])  -- thread per c (coalesced)
    for (int c = t; c < C_; c += 256) {
        float acc = b2[c];
#pragma unroll
        for (int j = 0; j < CH_; ++j)
            acc += hs[j] * g_W2cT[j * C_ + c];
        float yv = 1.f / (1.f + expf(-acc));
        ys[c] = yv;
        if (kg == 0) g_ys[b * C_ + c] = yv;
    }
    __syncthreads();

    // spectral bin k: DFT + s1/s2 matvecs + amp/phase rescale -- warp per k
    const int k = kg * 8 + w;
    if (k >= CF_) return;

    float re = 0.f, im = 0.f, a1 = 0.f, a2 = 0.f;
#pragma unroll
    for (int i = 0; i < 12; ++i) {
        int   n  = lane + 32 * i;
        float yv = ys[n];
        int   m  = (k * n) % C_;
        re += yv * cT[m];
        im -= yv * sT[m];
        a1 += yv * Ws1[k * C_ + n];
        a2 += yv * Ws2[k * C_ + n];
    }
#pragma unroll
    for (int o = 16; o > 0; o >>= 1) {
        re += __shfl_down_sync(0xffffffffu, re, o);
        im += __shfl_down_sync(0xffffffffu, im, o);
        a1 += __shfl_down_sync(0xffffffffu, a1, o);
        a2 += __shfl_down_sync(0xffffffffu, a2, o);
    }
    if (lane == 0) {
        float s1  = fmaxf(a1 + bs1[k], 0.f);
        float s2  = fmaxf(a2 + bs2[k], 0.f);
        float amp = sqrtf(re * re + im * im) * s1;
        float ph  = atan2f(im, re) * s2;
        float sp, cp;
        sincosf(ph, &sp, &cp);
        g_rRe[b * CF_ + k] = amp * cp;
        g_rIm[b * CF_ + k] = amp * sp;
    }
}

// ---------------------------------------------------------------------------
// Kernel 3: irfft(n=384) + gate multiply. Block = (b, group of 8 outputs),
// grid = 16*48 = 768; warp per output n.
// xr[n] = (rRe0 + sum_{k=1}^{191} 2(rRe_k cos - rIm_k sin) + rRe192*(-1)^n)/384
// ---------------------------------------------------------------------------
__global__ __launch_bounds__(256) void k_irfft(float* __restrict__ out)
{
    const int b  = blockIdx.x / 48;
    const int ng = blockIdx.x - b * 48;
    const int t  = threadIdx.x;
    const int lane = t & 31;

    __shared__ float sRe[CF_], sIm[CF_], cT[C_], sT[C_];
    for (int m = t; m < C_; m += 256) {
        cT[m] = g_cos[m];
        sT[m] = g_sin[m];
    }
    for (int m = t; m < CF_; m += 256) {
        sRe[m] = g_rRe[b * CF_ + m];
        sIm[m] = g_rIm[b * CF_ + m];
    }
    __syncthreads();

    const int n = ng * 8 + (t >> 5);

    float acc = 0.f;
#pragma unroll
    for (int i = 0; i < 6; ++i) {
        int   k   = 1 + lane + 32 * i;          // 1..192
        float wgt = (k == 192) ? 1.f : 2.f;
        int   m   = (k * n) % C_;
        acc += wgt * (sRe[k] * cT[m] - sIm[k] * sT[m]);
    }
#pragma unroll
    for (int o = 16; o > 0; o >>= 1) acc += __shfl_down_sync(0xffffffffu, acc, o);
    if (lane == 0) {
        float xr = (acc + sRe[0]) * (1.f / (float)C_);
        out[b * C_ + n] = xr * g_ys[b * C_ + n];
    }
}

// ---------------------------------------------------------------------------
extern "C" void kernel_launch(void* const* d_in, const int* in_sizes, int n_in,
                              void* d_out, int out_size) {
    const float* x   = (const float*)d_in[0];
    const float* W1  = (const float*)d_in[1];
    const float* b1  = (const float*)d_in[2];
    const float* W2  = (const float*)d_in[3];
    const float* b2  = (const float*)d_in[4];
    const float* Ws1 = (const float*)d_in[5];
    const float* bs1 = (const float*)d_in[6];
    const float* Ws2 = (const float*)d_in[7];
    const float* bs2 = (const float*)d_in[8];
    float* out = (float*)d_out;

    pool_kernel<<<B_ * C_, 256>>>(x, W1, W2);
    k_spec<<<B_ * 25, 256>>>(b1, b2, Ws1, bs1, Ws2, bs2);
    k_irfft<<<B_ * 48, 256>>>(out);
}

// round 5
// speedup vs baseline: 1.0033x; 1.0033x over previous
#include <cuda_runtime.h>
#include <math.h>

#define B_   16
#define C_   384
#define CH_  64
#define CF_  193
#define HW_  16384   // 128*128

__device__ float g_y0[B_ * C_];          // pooled means
__device__ float g_ys[B_ * C_];          // sigmoid gate y
__device__ float g_rRe[B_ * CF_];        // spectral re
__device__ float g_rIm[B_ * CF_];        // spectral im
__device__ float g_dftSC[CF_ * C_];      // fwd DFT cos, [k][n] (coalesced over n)
__device__ float g_dftSS[CF_ * C_];      // fwd DFT sin, [k][n]
__device__ float g_dftIC[C_ * CF_];      // irfft cos * wgt, [n][k] (coalesced over k)
__device__ float g_dftIS[C_ * CF_];      // irfft sin * wgt, [n][k]

// ---------------------------------------------------------------------------
// Kernel 1: global average pool. Clean stream, no side duties.
// One block per (b,c), 256 threads, float4 streaming loads.
// ---------------------------------------------------------------------------
__global__ __launch_bounds__(256) void pool_kernel(const float* __restrict__ x) {
    const int bc = blockIdx.x;
    const float4* __restrict__ p =
        reinterpret_cast<const float4*>(x + (size_t)bc * HW_);
    float s = 0.f;
#pragma unroll
    for (int i = 0; i < 16; ++i) {
        float4 v = __ldcs(p + threadIdx.x + 256 * i);
        s += (v.x + v.y) + (v.z + v.w);
    }
#pragma unroll
    for (int o = 16; o > 0; o >>= 1) s += __shfl_down_sync(0xffffffffu, s, o);
    __shared__ float ws[8];
    if ((threadIdx.x & 31) == 0) ws[threadIdx.x >> 5] = s;
    __syncthreads();
    if (threadIdx.x < 8) {
        s = ws[threadIdx.x];
#pragma unroll
        for (int o = 4; o > 0; o >>= 1) s += __shfl_down_sync(0xffu, s, o);
        if (threadIdx.x == 0) g_y0[bc] = s * (1.f / (float)HW_);
    }
}

// ---------------------------------------------------------------------------
// Kernel 2: SE gate (h -> y) per batch  +  cooperative DFT-table build.
// 16 blocks x 384 threads.
// ---------------------------------------------------------------------------
__global__ __launch_bounds__(384) void k_sey(
    const float* __restrict__ W1, const float* __restrict__ b1,
    const float* __restrict__ W2, const float* __restrict__ b2)
{
    const int b    = blockIdx.x;
    const int t    = threadIdx.x;      // 0..383
    const int w    = t >> 5;
    const int lane = t & 31;

    __shared__ float cT[C_], sT[C_], y0s[C_], hs[CH_];

    // base twiddles (exact angles)
    {
        float sv, cv;
        sincosf((float)t * (6.283185307179586f / (float)C_), &sv, &cv);
        cT[t] = cv;
        sT[t] = sv;
    }
    y0s[t] = g_y0[b * C_ + t];
    __syncthreads();

    // ---- table build: each block owns a slice of the 74112-entry tables ----
    {
        const int NTOT = CF_ * C_;                     // 74112
        const int lo = (NTOT * b) / B_, hi = (NTOT * (b + 1)) / B_;
        // forward tables [k][n]
        for (int e = lo + t; e < hi; e += C_) {
            int k = e / C_, n = e - k * C_;
            int m = (k * n) % C_;
            g_dftSC[e] = cT[m];
            g_dftSS[e] = sT[m];
        }
        // inverse tables [n][k], weight-folded: wgt = 2 for 1<=k<=191, else 1
        for (int e = lo + t; e < hi; e += C_) {
            int n = e / CF_, k = e - n * CF_;
            int m = (k * n) % C_;
            float wgt = (k >= 1 && k <= 191) ? 2.f : 1.f;
            g_dftIC[e] = wgt * cT[m];
            g_dftIS[e] = wgt * sT[m];
        }
    }

    // ---- h[j] = relu(y0 . W1[j,:,1,1] + b1[j]) : warp per j ----
    for (int j = w; j < CH_; j += 12) {
        float acc = 0.f;
#pragma unroll
        for (int i = 0; i < 12; ++i) {
            int n = lane + 32 * i;
            acc += y0s[n] * W1[j * (C_ * 9) + n * 9 + 4];
        }
#pragma unroll
        for (int o = 16; o > 0; o >>= 1) acc += __shfl_down_sync(0xffffffffu, acc, o);
        if (lane == 0) hs[j] = fmaxf(acc + b1[j], 0.f);
    }
    __syncthreads();

    // ---- y[c] = sigmoid(h . W2[c,:,1,1] + b2[c]) : thread per c ----
    {
        float acc = b2[t];
#pragma unroll
        for (int j = 0; j < CH_; ++j)
            acc += hs[j] * W2[t * (CH_ * 9) + j * 9 + 4];
        g_ys[b * C_ + t] = 1.f / (1.f + expf(-acc));
    }
}

// ---------------------------------------------------------------------------
// Kernel 3: spectral bins. Block = (b, 8 bins), grid 400. Warp per k.
// All inner-loop streams coalesced / conflict-free.
// ---------------------------------------------------------------------------
__global__ __launch_bounds__(256) void k_spec(
    const float* __restrict__ Ws1, const float* __restrict__ bs1,
    const float* __restrict__ Ws2, const float* __restrict__ bs2)
{
    const int b    = blockIdx.x / 25;
    const int kg   = blockIdx.x - b * 25;
    const int t    = threadIdx.x;
    const int lane = t & 31;

    __shared__ float ys[C_];
    for (int m = t; m < C_; m += 256) ys[m] = g_ys[b * C_ + m];
    __syncthreads();

    const int k = kg * 8 + (t >> 5);
    if (k >= CF_) return;

    const float* __restrict__ tc = g_dftSC + k * C_;
    const float* __restrict__ ts = g_dftSS + k * C_;
    const float* __restrict__ w1 = Ws1 + k * C_;
    const float* __restrict__ w2 = Ws2 + k * C_;

    float re = 0.f, im = 0.f, a1 = 0.f, a2 = 0.f;
#pragma unroll
    for (int i = 0; i < 12; ++i) {
        int   n  = lane + 32 * i;
        float yv = ys[n];
        re += yv * tc[n];
        im -= yv * ts[n];
        a1 += yv * w1[n];
        a2 += yv * w2[n];
    }
#pragma unroll
    for (int o = 16; o > 0; o >>= 1) {
        re += __shfl_down_sync(0xffffffffu, re, o);
        im += __shfl_down_sync(0xffffffffu, im, o);
        a1 += __shfl_down_sync(0xffffffffu, a1, o);
        a2 += __shfl_down_sync(0xffffffffu, a2, o);
    }
    if (lane == 0) {
        float s1  = fmaxf(a1 + bs1[k], 0.f);
        float s2  = fmaxf(a2 + bs2[k], 0.f);
        float amp = sqrtf(re * re + im * im) * s1;
        float ph  = atan2f(im, re) * s2;
        float sp, cp;
        sincosf(ph, &sp, &cp);
        g_rRe[b * CF_ + k] = amp * cp;
        g_rIm[b * CF_ + k] = amp * sp;
    }
}

// ---------------------------------------------------------------------------
// Kernel 4: irfft(n=384) + gate multiply. Block = (b, 8 outputs), grid 768.
// Warp per n; weights folded into the [n][k] tables, so:
//   xr[n] = (sum_{k=0}^{192} tabC[n][k]*rRe[k] - tabS[n][k]*rIm[k]) / 384
// ---------------------------------------------------------------------------
__global__ __launch_bounds__(256) void k_irfft(float* __restrict__ out)
{
    const int b  = blockIdx.x / 48;
    const int ng = blockIdx.x - b * 48;
    const int t  = threadIdx.x;
    const int lane = t & 31;

    __shared__ float sRe[CF_], sIm[CF_];
    for (int m = t; m < CF_; m += 256) {
        sRe[m] = g_rRe[b * CF_ + m];
        sIm[m] = g_rIm[b * CF_ + m];
    }
    __syncthreads();

    const int n = ng * 8 + (t >> 5);
    const float* __restrict__ tc = g_dftIC + n * CF_;
    const float* __restrict__ ts = g_dftIS + n * CF_;

    float acc = 0.f;
#pragma unroll
    for (int i = 0; i < 7; ++i) {
        int k = lane + 32 * i;                  // 0..192 (i=6: lane 0 only)
        if (k < CF_)
            acc += tc[k] * sRe[k] - ts[k] * sIm[k];
    }
#pragma unroll
    for (int o = 16; o > 0; o >>= 1) acc += __shfl_down_sync(0xffffffffu, acc, o);
    if (lane == 0) {
        float xr = acc * (1.f / (float)C_);
        out[b * C_ + n] = xr * g_ys[b * C_ + n];
    }
}

// ---------------------------------------------------------------------------
extern "C" void kernel_launch(void* const* d_in, const int* in_sizes, int n_in,
                              void* d_out, int out_size) {
    const float* x   = (const float*)d_in[0];
    const float* W1  = (const float*)d_in[1];
    const float* b1  = (const float*)d_in[2];
    const float* W2  = (const float*)d_in[3];
    const float* b2  = (const float*)d_in[4];
    const float* Ws1 = (const float*)d_in[5];
    const float* bs1 = (const float*)d_in[6];
    const float* Ws2 = (const float*)d_in[7];
    const float* bs2 = (const float*)d_in[8];
    float* out = (float*)d_out;

    pool_kernel<<<B_ * C_, 256>>>(x);
    k_sey<<<B_, C_>>>(W1, b1, W2, b2);
    k_spec<<<B_ * 25, 256>>>(Ws1, bs1, Ws2, bs2);
    k_irfft<<<B_ * 48, 256>>>(out);
}

// round 6
// speedup vs baseline: 1.1675x; 1.1636x over previous
#include <cuda_runtime.h>
#include <math.h>

#define B_   16
#define C_   384
#define CH_  64
#define CF_  193
#define HW_  16384   // 128*128
#define POOLB (B_ * C_)      // 6144 pooling blocks
#define SIDEB 96             // dedicated prep blocks appended after pool grid

__device__ float g_y0[B_ * C_];          // pooled means
__device__ float g_h [B_ * CH_];         // hidden relu
__device__ float g_ys[B_ * C_];          // sigmoid gate y
__device__ float g_rRe[B_ * CF_];        // spectral re
__device__ float g_rIm[B_ * CF_];        // spectral im
__device__ float g_W1c [CH_ * C_];       // W1 center taps   [j][n]
__device__ float g_W2cT[CH_ * C_];       // W2 center taps^T [j][c]
__device__ float g_dftSC[CF_ * C_];      // fwd DFT cos [k][n]
__device__ float g_dftSS[CF_ * C_];      // fwd DFT sin [k][n]
__device__ float g_dftIC[C_ * CF_];      // irfft cos*wgt [n][k]
__device__ float g_dftIS[C_ * CF_];      // irfft sin*wgt [n][k]

// ---------------------------------------------------------------------------
// Kernel 1: global average pool (blocks 0..6143, untouched hot path) plus
// 96 dedicated side blocks (6144..6239) that compact weights and build the
// DFT tables. Side blocks are scheduled last -> live in the tail wave.
// ---------------------------------------------------------------------------
__global__ __launch_bounds__(256) void pool_kernel(
    const float* __restrict__ x,
    const float* __restrict__ W1, const float* __restrict__ W2)
{
    const int bid = blockIdx.x;
    const int t   = threadIdx.x;

    if (bid >= POOLB) {
        const int s = bid - POOLB;                      // 0..95
        if (s < 6) {                                    // W1 center taps
            for (int e = s * 4096 + t; e < (s + 1) * 4096; e += 256) {
                int j = e / C_, n = e - j * C_;
                g_W1c[e] = W1[j * (C_ * 9) + n * 9 + 4];
            }
        } else if (s < 12) {                            // W2 center taps ^T
            for (int e = (s - 6) * 4096 + t; e < (s - 5) * 4096; e += 256) {
                int j = e / C_, c = e - j * C_;
                g_W2cT[e] = W2[c * (CH_ * 9) + j * 9 + 4];
            }
        } else {                                        // DFT tables
            __shared__ float cT[C_], sT[C_];
            for (int m = t; m < C_; m += 256) {
                float sv, cv;
                sincosf((float)m * (6.283185307179586f / (float)C_), &sv, &cv);
                cT[m] = cv;
                sT[m] = sv;
            }
            __syncthreads();
            const int NTOT = CF_ * C_;                  // 74112
            if (s < 54) {                               // forward [k][n]
                const int g = s - 12;                   // 0..41
                const int lo = (NTOT * g) / 42, hi = (NTOT * (g + 1)) / 42;
                for (int e = lo + t; e < hi; e += 256) {
                    int k = e / C_, n = e - k * C_;
                    int m = (k * n) % C_;
                    g_dftSC[e] = cT[m];
                    g_dftSS[e] = sT[m];
                }
            } else {                                    // inverse [n][k], wgt folded
                const int g = s - 54;                   // 0..41
                const int lo = (NTOT * g) / 42, hi = (NTOT * (g + 1)) / 42;
                for (int e = lo + t; e < hi; e += 256) {
                    int n = e / CF_, k = e - n * CF_;
                    int m = (k * n) % C_;
                    float wgt = (k >= 1 && k <= 191) ? 2.f : 1.f;
                    g_dftIC[e] = wgt * cT[m];
                    g_dftIS[e] = wgt * sT[m];
                }
            }
        }
        return;
    }

    const float4* __restrict__ p =
        reinterpret_cast<const float4*>(x + (size_t)bid * HW_);
    float s = 0.f;
#pragma unroll
    for (int i = 0; i < 16; ++i) {
        float4 v = __ldcs(p + t + 256 * i);
        s += (v.x + v.y) + (v.z + v.w);
    }
#pragma unroll
    for (int o = 16; o > 0; o >>= 1) s += __shfl_down_sync(0xffffffffu, s, o);
    __shared__ float ws[8];
    if ((t & 31) == 0) ws[t >> 5] = s;
    __syncthreads();
    if (t < 8) {
        s = ws[t];
#pragma unroll
        for (int o = 4; o > 0; o >>= 1) s += __shfl_down_sync(0xffu, s, o);
        if (t == 0) g_y0[bid] = s * (1.f / (float)HW_);
    }
}

// ---------------------------------------------------------------------------
// Kernel 2: h[b,j] = relu(y0[b,:] . W1c[j,:] + b1[j]).
// One warp per (b,j): 1024 warps, 128 blocks. Coalesced weights.
// ---------------------------------------------------------------------------
__global__ __launch_bounds__(256) void k_h(const float* __restrict__ b1)
{
    const int wid  = blockIdx.x * 8 + (threadIdx.x >> 5);   // 0..1023
    const int lane = threadIdx.x & 31;
    const int b = wid >> 6;
    const int j = wid & 63;
    const float* __restrict__ y0 = g_y0 + b * C_;
    const float* __restrict__ wr = g_W1c + j * C_;
    float acc = 0.f;
#pragma unroll
    for (int i = 0; i < 12; ++i) {
        int n = lane + 32 * i;
        acc += y0[n] * wr[n];
    }
#pragma unroll
    for (int o = 16; o > 0; o >>= 1) acc += __shfl_down_sync(0xffffffffu, acc, o);
    if (lane == 0) g_h[wid] = fmaxf(acc + b1[j], 0.f);
}

// ---------------------------------------------------------------------------
// Kernel 3: y[b,c] = sigmoid(h[b,:] . W2cT[:,c] + b2[c]).
// One thread per (b,c): 24 blocks x 256. Coalesced weights over c.
// ---------------------------------------------------------------------------
__global__ __launch_bounds__(256) void k_gate(const float* __restrict__ b2)
{
    const int bc = blockIdx.x * 256 + threadIdx.x;
    const int b = bc / C_;
    const int c = bc - b * C_;
    const float* __restrict__ h = g_h + b * CH_;
    float acc = b2[c];
#pragma unroll
    for (int j = 0; j < CH_; ++j)
        acc += h[j] * g_W2cT[j * C_ + c];
    g_ys[bc] = 1.f / (1.f + expf(-acc));
}

// ---------------------------------------------------------------------------
// Kernel 4: spectral bins. Block = (b, 8 bins), grid 400. Warp per k.
// All inner-loop streams coalesced (precomputed [k][n] tables).
// ---------------------------------------------------------------------------
__global__ __launch_bounds__(256) void k_spec(
    const float* __restrict__ Ws1, const float* __restrict__ bs1,
    const float* __restrict__ Ws2, const float* __restrict__ bs2)
{
    const int b    = blockIdx.x / 25;
    const int kg   = blockIdx.x - b * 25;
    const int t    = threadIdx.x;
    const int lane = t & 31;

    __shared__ float ys[C_];
    for (int m = t; m < C_; m += 256) ys[m] = g_ys[b * C_ + m];
    __syncthreads();

    const int k = kg * 8 + (t >> 5);
    if (k >= CF_) return;

    const float* __restrict__ tc = g_dftSC + k * C_;
    const float* __restrict__ ts = g_dftSS + k * C_;
    const float* __restrict__ w1 = Ws1 + k * C_;
    const float* __restrict__ w2 = Ws2 + k * C_;

    float re = 0.f, im = 0.f, a1 = 0.f, a2 = 0.f;
#pragma unroll
    for (int i = 0; i < 12; ++i) {
        int   n  = lane + 32 * i;
        float yv = ys[n];
        re += yv * tc[n];
        im -= yv * ts[n];
        a1 += yv * w1[n];
        a2 += yv * w2[n];
    }
#pragma unroll
    for (int o = 16; o > 0; o >>= 1) {
        re += __shfl_down_sync(0xffffffffu, re, o);
        im += __shfl_down_sync(0xffffffffu, im, o);
        a1 += __shfl_down_sync(0xffffffffu, a1, o);
        a2 += __shfl_down_sync(0xffffffffu, a2, o);
    }
    if (lane == 0) {
        float s1  = fmaxf(a1 + bs1[k], 0.f);
        float s2  = fmaxf(a2 + bs2[k], 0.f);
        float amp = sqrtf(re * re + im * im) * s1;
        float ph  = atan2f(im, re) * s2;
        float sp, cp;
        sincosf(ph, &sp, &cp);
        g_rRe[b * CF_ + k] = amp * cp;
        g_rIm[b * CF_ + k] = amp * sp;
    }
}

// ---------------------------------------------------------------------------
// Kernel 5: irfft(n=384) + gate multiply. Block = (b, 8 outputs), grid 768.
// Warp per n; weights folded into [n][k] tables:
//   xr[n] = (sum_k tabC[n][k]*rRe[k] - tabS[n][k]*rIm[k]) / 384
// ---------------------------------------------------------------------------
__global__ __launch_bounds__(256) void k_irfft(float* __restrict__ out)
{
    const int b  = blockIdx.x / 48;
    const int ng = blockIdx.x - b * 48;
    const int t  = threadIdx.x;
    const int lane = t & 31;

    __shared__ float sRe[CF_], sIm[CF_];
    for (int m = t; m < CF_; m += 256) {
        sRe[m] = g_rRe[b * CF_ + m];
        sIm[m] = g_rIm[b * CF_ + m];
    }
    __syncthreads();

    const int n = ng * 8 + (t >> 5);
    const float* __restrict__ tc = g_dftIC + n * CF_;
    const float* __restrict__ ts = g_dftIS + n * CF_;

    float acc = 0.f;
#pragma unroll
    for (int i = 0; i < 7; ++i) {
        int k = lane + 32 * i;                  // 0..192 (i=6: lane 0 only)
        if (k < CF_)
            acc += tc[k] * sRe[k] - ts[k] * sIm[k];
    }
#pragma unroll
    for (int o = 16; o > 0; o >>= 1) acc += __shfl_down_sync(0xffffffffu, acc, o);
    if (lane == 0) {
        float xr = acc * (1.f / (float)C_);
        out[b * C_ + n] = xr * g_ys[b * C_ + n];
    }
}

// ---------------------------------------------------------------------------
extern "C" void kernel_launch(void* const* d_in, const int* in_sizes, int n_in,
                              void* d_out, int out_size) {
    const float* x   = (const float*)d_in[0];
    const float* W1  = (const float*)d_in[1];
    const float* b1  = (const float*)d_in[2];
    const float* W2  = (const float*)d_in[3];
    const float* b2  = (const float*)d_in[4];
    const float* Ws1 = (const float*)d_in[5];
    const float* bs1 = (const float*)d_in[6];
    const float* Ws2 = (const float*)d_in[7];
    const float* bs2 = (const float*)d_in[8];
    float* out = (float*)d_out;

    pool_kernel<<<POOLB + SIDEB, 256>>>(x, W1, W2);
    k_h<<<B_ * CH_ / 8, 256>>>(b1);
    k_gate<<<B_ * C_ / 256, 256>>>(b2);
    k_spec<<<B_ * 25, 256>>>(Ws1, bs1, Ws2, bs2);
    k_irfft<<<B_ * 48, 256>>>(out);
}